// round 6
// baseline (speedup 1.0000x reference)
#include <cuda_runtime.h>

// SphereConv R6: cp.async.bulk (TMA engine) producer + mbarrier pipeline.
// Block=(b,l), 128 thr, all 8 f, 2 m/thread. Thread 0 issues 8x1KB bulk
// copies per stage (4c x {re,im}) with complete_tx; DEPTH=3 smem ring.
// No LDG/LDGSTS in hot loop -> L1tex carries only the LDS read side;
// DRAM latency hidden by bulk-copy MLP (no registers consumed in flight).

#define B_ 4
#define C_ 32
#define L_ 256
#define M_ 256
#define F_ 8
#define N_ 64
#define CH 4                 // c's per stage
#define DEPTH 3              // ring depth
#define NCH (C_ / CH)        // 8 stages
#define STAGE_BYTES (CH * 2 * M_ * 4)   // 8192

typedef unsigned long long u64;
typedef unsigned int u32;

__device__ __forceinline__ u64 pk2(float lo, float hi) {
    u64 r;
    asm("mov.b64 %0, {%1, %2};" : "=l"(r) : "f"(lo), "f"(hi));
    return r;
}
__device__ __forceinline__ void upk2(u64 v, float& lo, float& hi) {
    asm("mov.b64 {%0, %1}, %2;" : "=f"(lo), "=f"(hi) : "l"(v));
}
__device__ __forceinline__ u64 ffma2(u64 a, u64 b, u64 c) {
    u64 d;
    asm("fma.rn.f32x2 %0, %1, %2, %3;" : "=l"(d) : "l"(a), "l"(b), "l"(c));
    return d;
}
__device__ __forceinline__ void bulk_cp(u32 dst, const float* src, u32 bytes, u32 mbar) {
    asm volatile(
        "cp.async.bulk.shared::cluster.global.mbarrier::complete_tx::bytes "
        "[%0], [%1], %2, [%3];"
        :: "r"(dst), "l"(src), "r"(bytes), "r"(mbar) : "memory");
}
__device__ __forceinline__ void mbar_init(u32 mbar, u32 cnt) {
    asm volatile("mbarrier.init.shared.b64 [%0], %1;" :: "r"(mbar), "r"(cnt) : "memory");
}
__device__ __forceinline__ void mbar_expect_tx(u32 mbar, u32 bytes) {
    asm volatile("mbarrier.arrive.expect_tx.shared.b64 _, [%0], %1;"
                 :: "r"(mbar), "r"(bytes) : "memory");
}
__device__ __forceinline__ void mbar_wait(u32 mbar, u32 parity) {
    asm volatile(
        "{\n\t"
        ".reg .pred P;\n\t"
        "WL_%=:\n\t"
        "mbarrier.try_wait.parity.acquire.cta.shared::cta.b64 P, [%0], %1, 0x989680;\n\t"
        "@P bra.uni WD_%=;\n\t"
        "bra.uni WL_%=;\n\t"
        "WD_%=:\n\t"
        "}"
        :: "r"(mbar), "r"(parity) : "memory");
}

__global__ void __launch_bounds__(128, 7) sphere_conv_kernel(
    const float* __restrict__ xr, const float* __restrict__ xi,
    const float* __restrict__ wr, const float* __restrict__ wi,
    float* __restrict__ out)
{
    __shared__ __align__(16) float xbuf[DEPTH][CH][2][M_];   // 24 KB ring
    __shared__ __align__(16) u64 swr[C_ * F_];
    __shared__ __align__(16) u64 swi[C_ * F_];
    __shared__ __align__(16) u64 snw[C_ * F_];
    __shared__ __align__(8)  u64 mbar_full[DEPTH];

    const int b   = blockIdx.x;
    const int l   = blockIdx.y;
    const int tid = threadIdx.x;

    // --- weight interpolation: 256 (f,c) pairs, 2 per thread ---
    {
        float t = ((float)l / (float)(L_ - 1)) * (float)(N_ - 1);
        int lo = (int)floorf(t);
        lo = lo < 0 ? 0 : (lo > N_ - 2 ? N_ - 2 : lo);
        const float fr = t - (float)lo;
        const float s  = sqrtf(1.0f + (float)l) * (1.0f / (float)C_);
        #pragma unroll
        for (int kk = 0; kk < 2; ++kk) {
            const int idx = tid + kk * 128;
            const int f = idx >> 5, c = idx & 31;
            const int base = (f * C_ + c) * N_ + lo;
            float wrv = wr[base] * (1.0f - fr) + wr[base + 1] * fr;
            float wiv = wi[base] * (1.0f - fr) + wi[base + 1] * fr;
            wrv *= s; wiv *= s;
            swr[c * F_ + f] = pk2(wrv, wrv);
            swi[c * F_ + f] = pk2(wiv, wiv);
            snw[c * F_ + f] = pk2(-wiv, -wiv);
        }
    }

    const u32 mb0  = (u32)__cvta_generic_to_shared(&mbar_full[0]);
    const u32 buf0 = (u32)__cvta_generic_to_shared(&xbuf[0][0][0][0]);

    if (tid == 0) {
        #pragma unroll
        for (int s = 0; s < DEPTH; ++s) mbar_init(mb0 + s * 8, 1);
    }
    __syncthreads();   // weights visible + mbarriers initialized

    // --- producer (thread 0): issue one stage = 8 x 1KB bulk copies ---
    const u64 rowStride = (u64)L_ * M_;          // floats between c's
    const float* xrb = xr + ((u64)(b * C_) * L_ + l) * M_;
    const float* xib = xi + ((u64)(b * C_) * L_ + l) * M_;

    auto stage = [&](int k) {
        const u32 mb = mb0 + (u32)(k % DEPTH) * 8;
        mbar_expect_tx(mb, STAGE_BYTES);
        const u32 d = buf0 + (u32)(k % DEPTH) * STAGE_BYTES;
        #pragma unroll
        for (int ci = 0; ci < CH; ++ci) {
            const u64 coff = (u64)(k * CH + ci) * rowStride;
            bulk_cp(d + (u32)(ci * 2) * (M_ * 4),     xrb + coff, M_ * 4, mb);
            bulk_cp(d + (u32)(ci * 2 + 1) * (M_ * 4), xib + coff, M_ * 4, mb);
        }
    };

    if (tid == 0) { stage(0); stage(1); stage(2); }

    const int m0 = tid << 1;   // 2 m per thread

    u64 aR[F_], aI[F_];
    #pragma unroll
    for (int f = 0; f < F_; ++f) { aR[f] = 0ull; aI[f] = 0ull; }

    #pragma unroll 1
    for (int k = 0; k < NCH; ++k) {
        mbar_wait(mb0 + (u32)(k % DEPTH) * 8, (u32)((k / DEPTH) & 1));

        const int bufi = k % DEPTH;
        #pragma unroll
        for (int cc = 0; cc < CH; ++cc) {
            const int c = k * CH + cc;
            const u64 x_r = *(const u64*)&xbuf[bufi][cc][0][m0];
            const u64 x_i = *(const u64*)&xbuf[bufi][cc][1][m0];
            const ulonglong2* __restrict__ pwr = (const ulonglong2*)(swr + c * F_);
            const ulonglong2* __restrict__ pwi = (const ulonglong2*)(swi + c * F_);
            const ulonglong2* __restrict__ pnw = (const ulonglong2*)(snw + c * F_);
            #pragma unroll
            for (int fp = 0; fp < F_ / 2; ++fp) {
                const ulonglong2 w_r = pwr[fp];
                const ulonglong2 w_i = pwi[fp];
                const ulonglong2 w_n = pnw[fp];
                const int f0 = fp * 2;
                aR[f0]   = ffma2(w_r.x, x_r, aR[f0]);
                aR[f0]   = ffma2(w_n.x, x_i, aR[f0]);
                aI[f0]   = ffma2(w_r.x, x_i, aI[f0]);
                aI[f0]   = ffma2(w_i.x, x_r, aI[f0]);
                aR[f0+1] = ffma2(w_r.y, x_r, aR[f0+1]);
                aR[f0+1] = ffma2(w_n.y, x_i, aR[f0+1]);
                aI[f0+1] = ffma2(w_r.y, x_i, aI[f0+1]);
                aI[f0+1] = ffma2(w_i.y, x_r, aI[f0+1]);
            }
        }

        __syncthreads();                       // buffer fully consumed
        if (tid == 0 && k + DEPTH < NCH) stage(k + DEPTH);
    }

    // --- epilogue: relu on real only, write (2, B, F, L, M) ---
    const int outHalf = B_ * F_ * L_ * M_;
    #pragma unroll
    for (int f = 0; f < F_; ++f) {
        const int oR = ((b * F_ + f) * L_ + l) * M_ + m0;
        float r0, r1, i0, i1;
        upk2(aR[f], r0, r1);
        upk2(aI[f], i0, i1);
        *(float2*)(out + oR)           = make_float2(fmaxf(r0, 0.0f), fmaxf(r1, 0.0f));
        *(float2*)(out + outHalf + oR) = make_float2(i0, i1);
    }
}

extern "C" void kernel_launch(void* const* d_in, const int* in_sizes, int n_in,
                              void* d_out, int out_size) {
    const float* xr = (const float*)d_in[0];
    const float* xi = (const float*)d_in[1];
    const float* wr = (const float*)d_in[2];
    const float* wi = (const float*)d_in[3];
    float* out = (float*)d_out;
    dim3 grid(B_, L_);   // (b, l): 1024 blocks, 7 CTAs/SM, single wave
    sphere_conv_kernel<<<grid, 128>>>(xr, xi, wr, wi, out);
}

// round 7
// speedup vs baseline: 1.3750x; 1.3750x over previous
#include <cuda_runtime.h>

// SphereConv R7: register-pipelined loads + split accumulators.
// Block 128 thr = (b x mq), each thread 4 m (float4 LDG) x 4 f.
// Grid = fh(2) x mh(2) x l(256) = 1024. launch_bounds(128,6) -> 85-reg
// budget leaves room for explicit 1-deep x prefetch (structural MLP).
// Split accums (Rp = sum wr*xr, Rm = sum wi*xi, I) kill the -wi smem array:
// 4 LDS.128 weights per c. Epilogue: r = relu(p - m).

#define B_ 4
#define C_ 32
#define L_ 256
#define M_ 256
#define F_ 8
#define N_ 64
#define FH 4

typedef unsigned long long u64;

__device__ __forceinline__ u64 pk2(float lo, float hi) {
    u64 r;
    asm("mov.b64 %0, {%1, %2};" : "=l"(r) : "f"(lo), "f"(hi));
    return r;
}
__device__ __forceinline__ void upk2(u64 v, float& lo, float& hi) {
    asm("mov.b64 {%0, %1}, %2;" : "=f"(lo), "=f"(hi) : "l"(v));
}
__device__ __forceinline__ u64 ffma2(u64 a, u64 b, u64 c) {
    u64 d;
    asm("fma.rn.f32x2 %0, %1, %2, %3;" : "=l"(d) : "l"(a), "l"(b), "l"(c));
    return d;
}

__global__ void __launch_bounds__(128, 6) sphere_conv_kernel(
    const float* __restrict__ xr, const float* __restrict__ xi,
    const float* __restrict__ wr, const float* __restrict__ wi,
    float* __restrict__ out)
{
    __shared__ __align__(16) u64 swr[C_ * FH];   // {s*wr, s*wr} per (c, f_local)
    __shared__ __align__(16) u64 swi[C_ * FH];   // {s*wi, s*wi}

    const int fh  = blockIdx.x & 1;
    const int mh  = blockIdx.x >> 1;
    const int l   = blockIdx.y;
    const int tid = threadIdx.x;

    // --- weight interpolation: 128 (f_local, c) pairs == 128 threads ---
    {
        const int fl = tid >> 5;
        const int c  = tid & 31;
        const int f  = fh * FH + fl;
        float t = ((float)l / (float)(L_ - 1)) * (float)(N_ - 1);
        int lo = (int)floorf(t);
        lo = lo < 0 ? 0 : (lo > N_ - 2 ? N_ - 2 : lo);
        const float fr = t - (float)lo;
        const int base = (f * C_ + c) * N_ + lo;
        float wrv = wr[base] * (1.0f - fr) + wr[base + 1] * fr;
        float wiv = wi[base] * (1.0f - fr) + wi[base + 1] * fr;
        const float s = sqrtf(1.0f + (float)l) * (1.0f / (float)C_);
        wrv *= s; wiv *= s;
        swr[c * FH + fl] = pk2(wrv, wrv);
        swi[c * FH + fl] = pk2(wiv, wiv);
    }
    __syncthreads();

    const int b  = tid >> 5;
    const int mq = tid & 31;
    const int m0 = (mh << 7) + (mq << 2);     // 4 m per thread

    const int base4 = (((b * C_) * L_ + l) * M_ + m0) >> 2;
    const int cstr4 = (L_ * M_) >> 2;

    const float4* __restrict__ xr4 = (const float4*)xr;
    const float4* __restrict__ xi4 = (const float4*)xi;

    // split accumulators: Rp = sum wr*x_r, Rm = sum wi*x_i, I = sum wr*x_i + wi*x_r
    u64 aRp[FH][2], aRm[FH][2], aI[FH][2];
    #pragma unroll
    for (int f = 0; f < FH; ++f) {
        aRp[f][0] = aRp[f][1] = 0ull;
        aRm[f][0] = aRm[f][1] = 0ull;
        aI [f][0] = aI [f][1] = 0ull;
    }

    // --- software-pipelined c loop: load x[c+1] before computing c ---
    float4 vr = xr4[base4];
    float4 vi = xi4[base4];

    #pragma unroll
    for (int c = 0; c < C_; ++c) {
        const u64 x_r0 = pk2(vr.x, vr.y), x_r1 = pk2(vr.z, vr.w);
        const u64 x_i0 = pk2(vi.x, vi.y), x_i1 = pk2(vi.z, vi.w);
        if (c + 1 < C_) {                    // prefetch next c
            vr = xr4[base4 + (c + 1) * cstr4];
            vi = xi4[base4 + (c + 1) * cstr4];
        }

        const ulonglong2* __restrict__ pwr = (const ulonglong2*)(swr + c * FH);
        const ulonglong2* __restrict__ pwi = (const ulonglong2*)(swi + c * FH);

        #pragma unroll
        for (int fp = 0; fp < FH / 2; ++fp) {
            const ulonglong2 w_r = pwr[fp];
            const ulonglong2 w_i = pwi[fp];
            const int f0 = fp * 2;
            aRp[f0][0]   = ffma2(w_r.x, x_r0, aRp[f0][0]);
            aRm[f0][0]   = ffma2(w_i.x, x_i0, aRm[f0][0]);
            aI [f0][0]   = ffma2(w_r.x, x_i0, aI [f0][0]);
            aI [f0][0]   = ffma2(w_i.x, x_r0, aI [f0][0]);
            aRp[f0][1]   = ffma2(w_r.x, x_r1, aRp[f0][1]);
            aRm[f0][1]   = ffma2(w_i.x, x_i1, aRm[f0][1]);
            aI [f0][1]   = ffma2(w_r.x, x_i1, aI [f0][1]);
            aI [f0][1]   = ffma2(w_i.x, x_r1, aI [f0][1]);
            aRp[f0+1][0] = ffma2(w_r.y, x_r0, aRp[f0+1][0]);
            aRm[f0+1][0] = ffma2(w_i.y, x_i0, aRm[f0+1][0]);
            aI [f0+1][0] = ffma2(w_r.y, x_i0, aI [f0+1][0]);
            aI [f0+1][0] = ffma2(w_i.y, x_r0, aI [f0+1][0]);
            aRp[f0+1][1] = ffma2(w_r.y, x_r1, aRp[f0+1][1]);
            aRm[f0+1][1] = ffma2(w_i.y, x_i1, aRm[f0+1][1]);
            aI [f0+1][1] = ffma2(w_r.y, x_i1, aI [f0+1][1]);
            aI [f0+1][1] = ffma2(w_i.y, x_r1, aI [f0+1][1]);
        }
    }

    // --- epilogue: r = relu(p - m), write (2, B, F, L, M) ---
    const int outHalf = B_ * F_ * L_ * M_;
    #pragma unroll
    for (int fl = 0; fl < FH; ++fl) {
        const int f  = fh * FH + fl;
        const int oR = ((b * F_ + f) * L_ + l) * M_ + m0;
        float p0, p1, p2, p3, q0, q1, q2, q3, i0, i1, i2, i3;
        upk2(aRp[fl][0], p0, p1); upk2(aRp[fl][1], p2, p3);
        upk2(aRm[fl][0], q0, q1); upk2(aRm[fl][1], q2, q3);
        upk2(aI [fl][0], i0, i1); upk2(aI [fl][1], i2, i3);
        *(float4*)(out + oR) = make_float4(
            fmaxf(p0 - q0, 0.0f), fmaxf(p1 - q1, 0.0f),
            fmaxf(p2 - q2, 0.0f), fmaxf(p3 - q3, 0.0f));
        *(float4*)(out + outHalf + oR) = make_float4(i0, i1, i2, i3);
    }
}

extern "C" void kernel_launch(void* const* d_in, const int* in_sizes, int n_in,
                              void* d_out, int out_size) {
    const float* xr = (const float*)d_in[0];
    const float* xi = (const float*)d_in[1];
    const float* wr = (const float*)d_in[2];
    const float* wi = (const float*)d_in[3];
    float* out = (float*)d_out;
    dim3 grid(4, L_);   // (fh|mh, l) — fh fastest: f-half pairs co-resident
    sphere_conv_kernel<<<grid, 128>>>(xr, xi, wr, wi, out);
}